// round 17
// baseline (speedup 1.0000x reference)
#include <cuda_runtime.h>
#include <cstdint>

#define SEQ   2048
#define BATCH 64
#define DIN   128
#define DH    256
#define G3    (3*DH)   // 768

#define NCL   8        // recurrence clusters
#define NP    8        // CTAs per cluster
#define GW    80       // gi worker CTAs
#define NTILE 1024     // gi M-tiles (128 rows each = 2 s-steps)
#define BPG   4        // batches per group
#define UPB   32       // hidden units per block
#define ROWSB 96       // 3*UPB gate rows per block
#define SLICE 128      // floats per h slice
#define HBUF  1024     // floats per h buffer
#define PARTW 9
#define PARTN (384*PARTW)

// ---------------- scratch (device globals) ----------------
__device__ float g_gi[(size_t)SEQ * BATCH * G3];
__device__ float g_outs[(size_t)SEQ * BATCH * DH];
__device__ float g_scores[SEQ * BATCH];
__device__ float g_wpart[8 * BATCH * DH];
__device__ unsigned int g_prog[GW];   // worker j: tiles j,j+80,... completed count

// ---------------- helpers ----------------
__device__ __forceinline__ void fma2(unsigned long long& acc,
                                     unsigned long long a,
                                     unsigned long long b) {
    asm volatile("fma.rn.f32x2 %0, %1, %2, %0;" : "+l"(acc) : "l"(a), "l"(b));
}
__device__ __forceinline__ float2 u2f2(unsigned long long v) {
    float2 f;
    asm("mov.b64 {%0, %1}, %2;" : "=f"(f.x), "=f"(f.y) : "l"(v));
    return f;
}
__device__ __forceinline__ uint32_t smem_u32(const void* p) {
    return (uint32_t)__cvta_generic_to_shared(p);
}
__device__ __forceinline__ uint32_t cluster_rank() {
    uint32_t r; asm("mov.u32 %0, %%cluster_ctarank;" : "=r"(r)); return r;
}
__device__ __forceinline__ uint32_t mapa_sh(uint32_t local, uint32_t rank) {
    uint32_t r;
    asm("mapa.shared::cluster.u32 %0, %1, %2;" : "=r"(r) : "r"(local), "r"(rank));
    return r;
}
__device__ __forceinline__ void mbar_init(uint32_t a, uint32_t cnt) {
    asm volatile("mbarrier.init.shared.b64 [%0], %1;" :: "r"(a), "r"(cnt) : "memory");
}
__device__ __forceinline__ void mbar_expect_tx(uint32_t a, uint32_t tx) {
    asm volatile("mbarrier.arrive.expect_tx.shared.b64 _, [%0], %1;"
                 :: "r"(a), "r"(tx) : "memory");
}
__device__ __forceinline__ void bulk_push(uint32_t dst_cluster, uint32_t src_cta,
                                          uint32_t bytes, uint32_t mbar_cluster) {
    asm volatile(
        "cp.async.bulk.shared::cluster.shared::cta.mbarrier::complete_tx::bytes "
        "[%0], [%1], %2, [%3];"
        :: "r"(dst_cluster), "r"(src_cta), "r"(bytes), "r"(mbar_cluster) : "memory");
}
__device__ __forceinline__ void mbar_wait(uint32_t a, uint32_t ph) {
    uint32_t done;
    asm volatile(
        "{\n\t.reg .pred P;\n\t"
        "mbarrier.try_wait.parity.acquire.cta.shared::cta.b64 P, [%1], %2;\n\t"
        "selp.b32 %0, 1, 0, P;\n\t}"
        : "=r"(done) : "r"(a), "r"(ph) : "memory");
    while (!done) {
        asm volatile(
            "{\n\t.reg .pred P;\n\t"
            "mbarrier.try_wait.parity.acquire.cta.shared::cta.b64 P, [%1], %2, 0x989680;\n\t"
            "selp.b32 %0, 1, 0, P;\n\t}"
            : "=r"(done) : "r"(a), "r"(ph) : "memory");
    }
}
__device__ __forceinline__ unsigned ld_acq(const unsigned* p) {
    unsigned v;
    asm volatile("ld.global.acquire.gpu.u32 %0, [%1];" : "=r"(v) : "l"(p) : "memory");
    return v;
}
__device__ __forceinline__ void st_rel(unsigned* p, unsigned v) {
    asm volatile("st.global.release.gpu.u32 [%0], %1;" :: "l"(p), "r"(v) : "memory");
}
#define CLUSTER_SYNC_() do { \
    asm volatile("barrier.cluster.arrive.aligned;" ::: "memory"); \
    asm volatile("barrier.cluster.wait.aligned;" ::: "memory"); \
} while (0)

__device__ __forceinline__ float fsigmoid(float x) {
    float e = __expf(-x);
    return __fdividef(1.0f, 1.0f + e);
}
__device__ __forceinline__ float ftanh_fast(float x) {
    float e2 = __expf(2.0f * x);
    return 1.0f - __fdividef(2.0f, e2 + 1.0f);
}

__global__ void k_init() {
    if (threadIdx.x < GW) g_prog[threadIdx.x] = 0u;
}
__global__ void k_nop() {}

// ================= fused kernel: gi workers + GRU recurrence =================
__global__ void __launch_bounds__(256, 1) __cluster_dims__(NP, 1, 1)
fused_rnn(const float* __restrict__ X,
          const float* __restrict__ Wih,
          const float* __restrict__ bih,
          const float* __restrict__ Whh,
          const float* __restrict__ bhh_g) {
    extern __shared__ float sm[];
    const int tid = threadIdx.x;

    // ======================= WORKER PATH: gi GEMM ==========================
    if (blockIdx.x >= NCL * NP) {
        const int j = blockIdx.x - NCL * NP;    // worker 0..79
        float* As = sm;                // 128 x 132
        float* Bs = sm + 128 * 132;    // 128 x 132
        __shared__ unsigned char maskf[128];

        unsigned done = 0;
        for (int t = j; t < NTILE; t += GW) {
            const int m0 = t * 128;
            if (tid < 128) maskf[tid] = (X[(size_t)(m0 + tid) * DIN + 127] > 0.0f) ? 1 : 0;
            __syncthreads();

            for (int nb = 0; nb < 6; nb++) {
                const int n0 = nb * 128;
#pragma unroll
                for (int it = 0; it < 16; it++) {
                    int tt = tid + it * 256;
                    int r = tt >> 5, kk = tt & 31;
                    float4 va = *(const float4*)&X[(size_t)(m0 + r) * DIN + kk * 4];
                    if (maskf[r] && kk >= 8 && kk < 16) va = make_float4(0.f, 0.f, 0.f, 0.f);
                    *(float4*)&As[r * 132 + kk * 4] = va;
                    float4 vb = *(const float4*)&Wih[(size_t)(n0 + r) * DIN + kk * 4];
                    *(float4*)&Bs[r * 132 + kk * 4] = vb;
                }
                __syncthreads();

                const int tx = tid & 15;
                const int ty = tid >> 4;
                unsigned long long acc[8][8];
#pragma unroll
                for (int i = 0; i < 8; i++)
#pragma unroll
                    for (int jj = 0; jj < 8; jj++) acc[i][jj] = 0ull;

#pragma unroll 8
                for (int p = 0; p < 64; p++) {
                    unsigned long long av[8], bv[8];
#pragma unroll
                    for (int i = 0; i < 8; i++)
                        av[i] = *(const unsigned long long*)&As[(ty + 16 * i) * 132 + 2 * p];
#pragma unroll
                    for (int jj = 0; jj < 8; jj++)
                        bv[jj] = *(const unsigned long long*)&Bs[(tx + 16 * jj) * 132 + 2 * p];
#pragma unroll
                    for (int i = 0; i < 8; i++)
#pragma unroll
                        for (int jj = 0; jj < 8; jj++) fma2(acc[i][jj], av[i], bv[jj]);
                }

                __syncthreads();
#pragma unroll
                for (int i = 0; i < 8; i++)
#pragma unroll
                    for (int jj = 0; jj < 8; jj++) {
                        float2 f = u2f2(acc[i][jj]);
                        As[(ty + 16 * i) * 132 + tx + 16 * jj] = f.x + f.y;
                    }
                __syncthreads();

#pragma unroll
                for (int it = 0; it < 16; it++) {
                    int tt = tid + it * 256;
                    int r = tt >> 5, kk = tt & 31;
                    float4 c = *(const float4*)&As[r * 132 + kk * 4];
                    float4 b = *(const float4*)&bih[n0 + kk * 4];
                    c.x += b.x; c.y += b.y; c.z += b.z; c.w += b.w;
                    *(float4*)&g_gi[(size_t)(m0 + r) * G3 + n0 + kk * 4] = c;
                }
                __syncthreads();   // As reused next nb
            }
            done++;
            if (tid == 0) st_rel(&g_prog[j], done);   // tile t complete
        }
        return;
    }

    // ===================== RECURRENCE PATH (R14 best) ======================
    float* h_sh = sm;                      // [g][buf][1024]
    float* stg  = sm + 4 * HBUF;           // [g][buf][128]
    float* part = stg + 4 * SLICE;         // [g][parity][384*9]
    __shared__ __align__(8) unsigned long long mbar[32];

    const uint32_t rank = cluster_rank();
    const int ut = (int)rank;              // unit tile 0..7
    const int cl = blockIdx.x >> 3;        // cluster 0..7

    const int kc = tid >> 4;               // 0..15 k-chunk
    const int rq = tid & 15;
    const int kbase = kc * 16;
    const int sw = tid >> 5;               // my warp == my h slice
    const int hoff = sw * SLICE + (kc & 1) * 16;
    const int lane = tid & 31;

    const int egrp = tid >> 7;             // warps 0-3 -> group 0, 4-7 -> group 1
    const int et   = tid & 127;
    const int eb   = et >> 5;
    const int eu   = et & 31;
    const int ug   = ut * UPB + eu;
    const int bg   = (cl * 2 + egrp) * BPG + eb;

    ulonglong2 Wr[6][4];
#pragma unroll
    for (int j = 0; j < 6; j++) {
        const int r = rq + 16 * j;
        const int g = r >> 5, uu = r & 31;
        const float* src = &Whh[(size_t)(g * DH + ut * UPB + uu) * DH + kbase];
#pragma unroll
        for (int q = 0; q < 4; q++)
            Wr[j][q] = *(const ulonglong2*)&src[q * 4];
    }

    const float bhh0 = bhh_g[0 * DH + ug];
    const float bhh1 = bhh_g[1 * DH + ug];
    const float bhh2 = bhh_g[2 * DH + ug];

    const uint32_t mb_local  = smem_u32(mbar);
    const uint32_t h_local   = smem_u32(h_sh);
    const uint32_t stg_local = smem_u32(stg);

    for (int i = tid; i < HBUF; i += 256) {
        h_sh[1 * HBUF + i] = 0.0f;
        h_sh[3 * HBUF + i] = 0.0f;
    }
    if (tid == 0) {
#pragma unroll
        for (int i = 0; i < 32; i++) {
            mbar_init(mb_local + i * 8, 1);
            mbar_expect_tx(mb_local + i * 8, SLICE * 4);
        }
    }
    __syncthreads();

    uint32_t peer_h[NP], peer_mb[NP];
#pragma unroll
    for (int r = 0; r < NP; r++) {
        peer_h[r]  = mapa_sh(h_local, (uint32_t)r);
        peer_mb[r] = mapa_sh(mb_local, (uint32_t)r);
    }

    CLUSTER_SYNC_();   // barriers armed before any push

    // gate on tile 0 (covers gi for s=0 and s=1)
    if (tid == 0) { while (ld_acq(&g_prog[0]) < 1u) {} }
    __syncthreads();

    float gir, giz, gin;
    {
        const size_t b0 = (size_t)bg * G3 + ug;
        gir = __ldcg(&g_gi[b0]);
        giz = __ldcg(&g_gi[b0 + DH]);
        gin = __ldcg(&g_gi[b0 + 2 * DH]);
    }

    for (int s = 0; s < SEQ; s++) {
        const int rb = (s - 1) & 1;
        const int wb = s & 1;
        const uint32_t pw = (uint32_t)(((s - 1) >> 1) & 1);

        // prefetch gi(s+1); tile ((s+1)>>1) certified one iteration earlier
        float girN = 0.f, gizN = 0.f, ginN = 0.f;
        if (s + 1 < SEQ) {
            const size_t b = ((size_t)(s + 1) * BATCH + bg) * G3 + ug;
            girN = __ldcg(&g_gi[b]);
            gizN = __ldcg(&g_gi[b + DH]);
            ginN = __ldcg(&g_gi[b + 2 * DH]);
        }

#pragma unroll
        for (int grp = 0; grp < 2; grp++) {
            if (s > 0) {
                const uint32_t mymb = mb_local +
                    (uint32_t)(grp * 16 * 8 + (sw * 2 + rb) * 8);
                mbar_wait(mymb, pw);
                if (lane == 0 && (tid & 16) == 0 && sw == (tid >> 5) && s + 2 < SEQ) {
                    // lane 0 of each slice warp re-arms (one thread per barrier)
                    mbar_expect_tx(mymb, SLICE * 4);
                }
            }

            const float* hbc = h_sh + (grp * 2 + rb) * HBUF;
            unsigned long long acc[4][6];
#pragma unroll
            for (int i = 0; i < 4; i++)
#pragma unroll
                for (int j = 0; j < 6; j++) acc[i][j] = 0ull;

#pragma unroll
            for (int q = 0; q < 4; q++) {
                ulonglong2 hq[4];
#pragma unroll
                for (int i = 0; i < 4; i++)
                    hq[i] = *(const ulonglong2*)&hbc[hoff + i * UPB + q * 4];
#pragma unroll
                for (int i = 0; i < 4; i++)
#pragma unroll
                    for (int j = 0; j < 6; j++) {
                        fma2(acc[i][j], hq[i].x, Wr[j][q].x);
                        fma2(acc[i][j], hq[i].y, Wr[j][q].y);
                    }
            }

            float* ppw = part + (grp * 2 + wb) * PARTN;
#pragma unroll
            for (int i = 0; i < 4; i++)
#pragma unroll
                for (int j = 0; j < 6; j++) {
                    float2 f = u2f2(acc[i][j]);
                    float v = f.x + f.y;
                    v += __shfl_xor_sync(0xffffffffu, v, 16);
                    if ((tid & 16) == 0)
                        ppw[(i * ROWSB + rq + 16 * j) * PARTW + (kc >> 1)] = v;
                }
            __syncthreads();

            if (egrp == grp) {
                const float* pp = part + (grp * 2 + wb) * PARTN;
                const float* hb = h_sh + (grp * 2 + rb) * HBUF;
                const int o_r = (eb * ROWSB + eu) * PARTW;
                const int o_z = (eb * ROWSB + UPB + eu) * PARTW;
                const int o_n = (eb * ROWSB + 2 * UPB + eu) * PARTW;
                float Ar = ((pp[o_r+0]+pp[o_r+1])+(pp[o_r+2]+pp[o_r+3])) +
                           ((pp[o_r+4]+pp[o_r+5])+(pp[o_r+6]+pp[o_r+7])) + (bhh0 + gir);
                float Az = ((pp[o_z+0]+pp[o_z+1])+(pp[o_z+2]+pp[o_z+3])) +
                           ((pp[o_z+4]+pp[o_z+5])+(pp[o_z+6]+pp[o_z+7])) + (bhh1 + giz);
                float An = ((pp[o_n+0]+pp[o_n+1])+(pp[o_n+2]+pp[o_n+3])) +
                           ((pp[o_n+4]+pp[o_n+5])+(pp[o_n+6]+pp[o_n+7])) + bhh2;
                const float rr = fsigmoid(Ar);
                const float zz = fsigmoid(Az);
                const float nn = ftanh_fast(fmaf(rr, An, gin));
                const float hold = hb[ut * SLICE + et];
                const float hnew = fmaf(zz, hold - nn, nn);

                float* sg = stg + (grp * 2 + wb) * SLICE;
                sg[et] = hnew;
                __syncwarp();
                if (eu == 0 && s + 1 < SEQ) {
                    asm volatile("fence.proxy.async.shared::cta;" ::: "memory");
                    const uint32_t src   = stg_local +
                        (uint32_t)(((grp * 2 + wb) * SLICE + eb * 32) * 4);
                    const uint32_t doff  = (uint32_t)((grp * 2 + wb) * HBUF * 4 +
                        ut * SLICE * 4 + eb * 128);
                    const uint32_t mboff = (uint32_t)(grp * 16 * 8 + (ut * 2 + wb) * 8);
#pragma unroll
                    for (int r = 0; r < NP; r++)
                        bulk_push(peer_h[r] + doff, src, 128, peer_mb[r] + mboff);
                }

                // AFTER the push: tid0 certifies the tile needed at iter s+1
                if (tid == 0 && s + 2 < SEQ) {
                    const int T = (s + 2) >> 1;
                    const unsigned need = (unsigned)(T / GW + 1);
                    const unsigned* fp = &g_prog[T % GW];
                    while (ld_acq(fp) < need) {}
                }

                g_outs[((size_t)s * BATCH + bg) * DH + ug] = hnew;
                gir = girN; giz = gizN; gin = ginN;
            }
        }
    }

    CLUSTER_SYNC_();
}

// ---------------- Phase 3: attention ----------------
__global__ void k_scores(const float* __restrict__ watt) {
    __shared__ float wsm[DH];
    const int tid = threadIdx.x;
    wsm[tid] = watt[tid];
    __syncthreads();
    const int s = blockIdx.x;
    const int w = tid >> 5, l = tid & 31;
#pragma unroll
    for (int bb = w; bb < BATCH; bb += 8) {
        const float* row = &g_outs[((size_t)s * BATCH + bb) * DH];
        float acc = 0.f;
#pragma unroll
        for (int k = l; k < DH; k += 32) acc = fmaf(row[k], wsm[k], acc);
#pragma unroll
        for (int o = 16; o > 0; o >>= 1) acc += __shfl_xor_sync(0xffffffffu, acc, o);
        if (l == 0) g_scores[s * BATCH + bb] = acc;
    }
}

__global__ void k_softmax() {
    __shared__ float red[256];
    const int b = blockIdx.x, tid = threadIdx.x;
    float mx = -1e30f;
    for (int s = tid; s < SEQ; s += 256) mx = fmaxf(mx, g_scores[s * BATCH + b]);
    red[tid] = mx; __syncthreads();
    for (int o = 128; o > 0; o >>= 1) { if (tid < o) red[tid] = fmaxf(red[tid], red[tid + o]); __syncthreads(); }
    mx = red[0]; __syncthreads();
    float sum = 0.f;
    for (int s = tid; s < SEQ; s += 256) sum += __expf(g_scores[s * BATCH + b] - mx);
    red[tid] = sum; __syncthreads();
    for (int o = 128; o > 0; o >>= 1) { if (tid < o) red[tid] += red[tid + o]; __syncthreads(); }
    const float inv = 1.0f / red[0];
    for (int s = tid; s < SEQ; s += 256)
        g_scores[s * BATCH + b] = __expf(g_scores[s * BATCH + b] - mx) * inv;
}

__global__ void k_wsum1() {
    const int b = blockIdx.x, c = blockIdx.y, h = threadIdx.x;
    float acc = 0.f;
    const int s0 = c * 256;
#pragma unroll 4
    for (int s = s0; s < s0 + 256; s++)
        acc = fmaf(__ldg(&g_scores[s * BATCH + b]),
                   g_outs[((size_t)s * BATCH + b) * DH + h], acc);
    g_wpart[(c * BATCH + b) * DH + h] = acc;
}

__global__ void k_wsum2(float* __restrict__ out) {
    const int b = blockIdx.x, h = threadIdx.x;
    float acc = 0.f;
#pragma unroll
    for (int c = 0; c < 8; c++) acc += g_wpart[(c * BATCH + b) * DH + h];
    out[b * DH + h] = acc;
}

// ---------------- launch ----------------
extern "C" void kernel_launch(void* const* d_in, const int* in_sizes, int n_in,
                              void* d_out, int out_size) {
    const float* data = (const float*)d_in[0];
    const float* Wih  = (const float*)d_in[1];
    const float* Whh  = (const float*)d_in[2];
    const float* bih  = (const float*)d_in[3];
    const float* bhh  = (const float*)d_in[4];
    const float* watt = (const float*)d_in[5];
    float* out = (float*)d_out;

    // worker path needs 2*128*132 floats = 135168 B (superset of gru's 73728 B)
    const int fused_smem = 2 * 128 * 132 * (int)sizeof(float);

    cudaFuncSetAttribute(fused_rnn, cudaFuncAttributeMaxDynamicSharedMemorySize, fused_smem);

    k_init<<<1, 128>>>();
    k_nop<<<1, 32>>>();                        // shims: keep fused_rnn in the
    k_nop<<<1, 32>>>();                        // ncu capture slot (4th launch)
    fused_rnn<<<NCL * NP + GW, 256, fused_smem>>>(data, Wih, bih, Whh, bhh);
    k_scores<<<SEQ, 256>>>(watt);
    k_softmax<<<BATCH, 256>>>();
    dim3 gw(BATCH, 8);
    k_wsum1<<<gw, 256>>>();
    k_wsum2<<<BATCH, 256>>>(out);
}